// round 1
// baseline (speedup 1.0000x reference)
#include <cuda_runtime.h>

#define SIZE 256
#define KP 64
#define NB 4
#define NPIX (SIZE * SIZE)

// ---- scratch (device globals; no allocations allowed) ----
__device__ float g_mask[NB * NPIX];
__device__ float g_sobel[NB * NPIX];
__device__ float g_pool[NB * NPIX];
__device__ unsigned int g_mn[NB];
__device__ unsigned int g_mx[NB];

// ---------------------------------------------------------------------------
// 0. reset per-batch min/max accumulators
// ---------------------------------------------------------------------------
__global__ void k_init() {
    int t = threadIdx.x;
    if (t < NB) {
        g_mn[t] = 0x7f7fffffu;  // FLT_MAX bits
        g_mx[t] = 0u;           // 0.0f bits (all values are >= 0)
    }
}

// ---------------------------------------------------------------------------
// 1. winding-number soft mask  (the hot kernel: 4 x 65536 px x 64 verts)
//    mesh[p] = (i/256, j/256) with p = i*256 + j
//    diff_k = c_k - mesh ; nxt_k = diff_{(k+1) mod K}
//    cross  = diff.y*nxt.x - diff.x*nxt.y
//    mask   = clip(|sum tanh(1e5*cross) * acos(clip(dot/(|d||n|)))| / 2pi, 0, 1)
// ---------------------------------------------------------------------------
__global__ void k_mask(const float* __restrict__ contour) {
    __shared__ float cx[KP + 1];
    __shared__ float cy[KP + 1];
    const int b = blockIdx.y;
    const int t = threadIdx.x;
    if (t <= KP) {               // index 64 duplicates vertex 0 -> branchless roll
        int k = t & (KP - 1);
        cx[t] = contour[b * KP * 2 + k * 2 + 0];
        cy[t] = contour[b * KP * 2 + k * 2 + 1];
    }
    __syncthreads();

    const int p = blockIdx.x * blockDim.x + t;
    const int i = p >> 8;
    const int j = p & 255;
    const float px = (float)i * (1.0f / SIZE);
    const float py = (float)j * (1.0f / SIZE);

    // carry diff/norm of vertex k across iterations: one sqrt per vertex
    float dxp = cx[0] - px;
    float dyp = cy[0] - py;
    float np_ = sqrtf(dxp * dxp + dyp * dyp);

    float acc = 0.0f;
#pragma unroll 8
    for (int k = 0; k < KP; k++) {
        float dxn = cx[k + 1] - px;
        float dyn = cy[k + 1] - py;
        float nn  = sqrtf(dxn * dxn + dyn * dyn);

        float cross = dyp * dxn - dxp * dyn;
        float dot   = dxp * dxn + dyp * dyn;

        float r = dot / (np_ * nn);
        r = fminf(fmaxf(r, -1.0f + 1e-5f), 1.0f - 1e-5f);
        float ang = acosf(r);
        float s   = tanhf(100000.0f * cross);
        acc = fmaf(s, ang, acc);

        dxp = dxn; dyp = dyn; np_ = nn;
    }

    float m = fabsf(acc) * 0.15915494309189535f;  // 1/(2*pi)
    m = fminf(fmaxf(m, 0.0f), 1.0f);
    g_mask[b * NPIX + p] = m;
}

// ---------------------------------------------------------------------------
// 2. Sobel magnitude (cross-correlation, zero pad) with borders zeroed
// ---------------------------------------------------------------------------
__global__ void k_sobel() {
    const int b = blockIdx.y;
    const int i = blockIdx.x;
    const int j = threadIdx.x;
    const float* __restrict__ m = g_mask + b * NPIX;

    float v = 0.0f;
    if (i > 0 && i < SIZE - 1 && j > 0 && j < SIZE - 1) {
        float a00 = m[(i - 1) * SIZE + j - 1];
        float a01 = m[(i - 1) * SIZE + j];
        float a02 = m[(i - 1) * SIZE + j + 1];
        float a10 = m[i * SIZE + j - 1];
        float a12 = m[i * SIZE + j + 1];
        float a20 = m[(i + 1) * SIZE + j - 1];
        float a21 = m[(i + 1) * SIZE + j];
        float a22 = m[(i + 1) * SIZE + j + 1];
        float gx = 2.0f * (a00 - a02) + 4.0f * (a10 - a12) + 2.0f * (a20 - a22);
        float gy = 2.0f * (a00 - a20) + 4.0f * (a01 - a21) + 2.0f * (a02 - a22);
        v = sqrtf(fmaxf(gx * gx + gy * gy, 1e-24f));
    }
    g_sobel[b * NPIX + i * SIZE + j] = v;
}

// ---------------------------------------------------------------------------
// 3. 3x3 maxpool (stride 1, pad 1, -inf pad == clamped window) fused with
//    per-batch min/max reduction (uint-punned atomics; values >= 0)
// ---------------------------------------------------------------------------
__global__ void k_pool() {
    const int b = blockIdx.y;
    const int i = blockIdx.x;
    const int j = threadIdx.x;
    const float* __restrict__ s = g_sobel + b * NPIX;

    float mx = -3.4e38f;
#pragma unroll
    for (int di = -1; di <= 1; di++) {
        int ii = i + di;
        if (ii < 0 || ii >= SIZE) continue;
#pragma unroll
        for (int dj = -1; dj <= 1; dj++) {
            int jj = j + dj;
            if (jj < 0 || jj >= SIZE) continue;
            mx = fmaxf(mx, s[ii * SIZE + jj]);
        }
    }
    g_pool[b * NPIX + i * SIZE + j] = mx;

    // block-level min/max reduce then one atomic per block
    float lmn = mx, lmx = mx;
#pragma unroll
    for (int off = 16; off > 0; off >>= 1) {
        lmn = fminf(lmn, __shfl_xor_sync(0xffffffffu, lmn, off));
        lmx = fmaxf(lmx, __shfl_xor_sync(0xffffffffu, lmx, off));
    }
    __shared__ float smn[8], smx[8];
    int lane = threadIdx.x & 31;
    int wid  = threadIdx.x >> 5;
    if (lane == 0) { smn[wid] = lmn; smx[wid] = lmx; }
    __syncthreads();
    if (wid == 0) {
        lmn = (lane < 8) ? smn[lane] : 3.4e38f;
        lmx = (lane < 8) ? smx[lane] : 0.0f;
#pragma unroll
        for (int off = 4; off > 0; off >>= 1) {
            lmn = fminf(lmn, __shfl_xor_sync(0xffffffffu, lmn, off));
            lmx = fmaxf(lmx, __shfl_xor_sync(0xffffffffu, lmx, off));
        }
        if (lane == 0) {
            atomicMin(&g_mn[b], __float_as_uint(lmn));
            atomicMax(&g_mx[b], __float_as_uint(lmx));
        }
    }
}

// ---------------------------------------------------------------------------
// 4. per-batch normalize
// ---------------------------------------------------------------------------
__global__ void k_norm(float* __restrict__ out) {
    const int b = blockIdx.y;
    const int p = blockIdx.x * blockDim.x + threadIdx.x;
    const float mn = __uint_as_float(g_mn[b]);
    const float mx = __uint_as_float(g_mx[b]);
    out[b * NPIX + p] = (g_pool[b * NPIX + p] - mn) / (mx - mn + 1e-9f);
}

// ---------------------------------------------------------------------------
extern "C" void kernel_launch(void* const* d_in, const int* in_sizes, int n_in,
                              void* d_out, int out_size) {
    const float* contour = (const float*)d_in[0];
    float* out = (float*)d_out;

    k_init<<<1, 32>>>();
    dim3 gm(NPIX / 256, NB);
    k_mask<<<gm, 256>>>(contour);
    dim3 g2(SIZE, NB);
    k_sobel<<<g2, SIZE>>>();
    k_pool<<<g2, SIZE>>>();
    dim3 gn(NPIX / 256, NB);
    k_norm<<<gn, 256>>>(out);
}

// round 3
// speedup vs baseline: 1.7981x; 1.7981x over previous
#include <cuda_runtime.h>

#define SIZE 256
#define KP 64
#define NB 4
#define NPIX (SIZE * SIZE)

typedef unsigned long long u64;

// ---- scratch (device globals; no allocations allowed) ----
__device__ float g_mask[NB * NPIX];
__device__ float g_pool[NB * NPIX];
__device__ unsigned int g_mn[NB];
__device__ unsigned int g_mx[NB];

// ---- packed f32x2 helpers (Blackwell sm_100+) ----
__device__ __forceinline__ u64 pk(float lo, float hi) {
    u64 r; asm("mov.b64 %0,{%1,%2};" : "=l"(r) : "f"(lo), "f"(hi)); return r;
}
__device__ __forceinline__ u64 pk2(float s) { return pk(s, s); }
__device__ __forceinline__ void unpk(u64 v, float& lo, float& hi) {
    asm("mov.b64 {%0,%1},%2;" : "=f"(lo), "=f"(hi) : "l"(v));
}
__device__ __forceinline__ u64 pfma(u64 a, u64 b, u64 c) {
    u64 d; asm("fma.rn.f32x2 %0,%1,%2,%3;" : "=l"(d) : "l"(a), "l"(b), "l"(c)); return d;
}
__device__ __forceinline__ u64 pmul(u64 a, u64 b) {
    u64 d; asm("mul.rn.f32x2 %0,%1,%2;" : "=l"(d) : "l"(a), "l"(b)); return d;
}
__device__ __forceinline__ u64 padd(u64 a, u64 b) {
    u64 d; asm("add.rn.f32x2 %0,%1,%2;" : "=l"(d) : "l"(a), "l"(b)); return d;
}
__device__ __forceinline__ float rsq(float x) { float y; asm("rsqrt.approx.f32 %0,%1;" : "=f"(y) : "f"(x)); return y; }
__device__ __forceinline__ float sqa(float x) { float y; asm("sqrt.approx.f32 %0,%1;" : "=f"(y) : "f"(x)); return y; }
__device__ __forceinline__ float tha(float x) { float y; asm("tanh.approx.f32 %0,%1;" : "=f"(y) : "f"(x)); return y; }

// ---------------------------------------------------------------------------
// 0. reset per-batch min/max accumulators
// ---------------------------------------------------------------------------
__global__ void k_init() {
    int t = threadIdx.x;
    if (t < NB) {
        g_mn[t] = 0x7f7fffffu;  // FLT_MAX bits
        g_mx[t] = 0u;           // 0.0f bits (pooled values are >= 0)
    }
}

// ---------------------------------------------------------------------------
// 1. winding-number soft mask — 2 same-row pixels per thread, packed f32x2.
//    dx depends only on the row, so it is scalar and shared by both pixels.
//    acos via A&S 4.4.46 (abs err 2e-8); tanh/rsqrt/sqrt via MUFU approx.
// ---------------------------------------------------------------------------
__global__ void k_mask(const float* __restrict__ contour) {
    __shared__ float cx[KP + 1];
    __shared__ float cy[KP + 1];
    const int b = blockIdx.y;
    const int t = threadIdx.x;
    if (t <= KP) {               // index 64 duplicates vertex 0 -> branchless roll
        int k = t & (KP - 1);
        cx[t] = contour[b * KP * 2 + k * 2 + 0];
        cy[t] = contour[b * KP * 2 + k * 2 + 1];
    }
    __syncthreads();

    const int p  = blockIdx.x * 512 + 2 * t;     // even pixel index
    const float px  = (float)(p >> 8) * (1.0f / SIZE);
    const float py0 = (float)(p & 255) * (1.0f / SIZE);
    const float py1 = py0 + (1.0f / SIZE);

    // packed constants
    const u64 NPY     = pk(-py0, -py1);
    const u64 ONE     = pk2(1.0f);
    const u64 NEG1    = pk2(-1.0f);
    const u64 HALFPI  = pk2(1.5707963267948966f);
    const u64 NHALFPI = pk2(-1.5707963267948966f);
    const u64 KBIG    = pk2(100000.0f);
    const u64 A7 = pk2(-0.0012624911f);
    const u64 A6 = pk2( 0.0066700901f);
    const u64 A5 = pk2(-0.0170881256f);
    const u64 A4 = pk2( 0.0308918810f);
    const u64 A3 = pk2(-0.0501743046f);
    const u64 A2 = pk2( 0.0889789874f);
    const u64 A1 = pk2(-0.2145988016f);
    const u64 A0 = pk2( 1.5707963050f);

    // carried state: diff to vertex k (dx scalar; dy, |d|^2 packed)
    float dxp = cx[0] - px;
    u64 DYP = padd(pk2(cy[0]), NPY);
    u64 NP2 = pfma(DYP, DYP, pk2(dxp * dxp));
    u64 ACC = pk2(0.0f);

#pragma unroll 8
    for (int k = 0; k < KP; k++) {
        float dxn = cx[k + 1] - px;
        u64 DYN = padd(pk2(cy[k + 1]), NPY);
        u64 NN2 = pfma(DYN, DYN, pk2(dxn * dxn));
        u64 CROSS = pfma(DYP, pk2(dxn), pmul(pk2(-dxp), DYN));
        u64 DOT   = pfma(DYP, DYN, pk2(dxp * dxn));
        u64 PROD  = pmul(NP2, NN2);

        float pr0, pr1; unpk(PROD, pr0, pr1);
        float d0, d1;   unpk(DOT, d0, d1);
        float r0 = d0 * rsq(pr0);
        float r1 = d1 * rsq(pr1);

        float e0 = copysignf(1.0f, r0);
        float e1 = copysignf(1.0f, r1);
        float x0 = fminf(fabsf(r0), 0.99999f);   // = clip to ±(1 - 1e-5)
        float x1 = fminf(fabsf(r1), 0.99999f);

        u64 X  = pk(x0, x1);
        u64 T2 = pfma(X, NEG1, ONE);             // 1 - |r|
        float t0, t1; unpk(T2, t0, t1);
        float s0 = sqa(t0);
        float s1 = sqa(t1);

        u64 P = A7;
        P = pfma(X, P, A6);
        P = pfma(X, P, A5);
        P = pfma(X, P, A4);
        P = pfma(X, P, A3);
        P = pfma(X, P, A2);
        P = pfma(X, P, A1);
        P = pfma(X, P, A0);
        u64 POS = pmul(pk(s0, s1), P);           // acos(|r|)

        u64 E   = pk(e0, e1);
        u64 H   = pfma(E, NHALFPI, HALFPI);      // 0 if r>=0, pi if r<0
        u64 ANG = pfma(E, POS, H);               // acos(r)

        u64 CS = pmul(KBIG, CROSS);
        float c0, c1; unpk(CS, c0, c1);
        float th0 = tha(c0);
        float th1 = tha(c1);
        ACC = pfma(pk(th0, th1), ANG, ACC);

        dxp = dxn; DYP = DYN; NP2 = NN2;
    }

    float a0, a1; unpk(ACC, a0, a1);
    float m0 = fminf(fabsf(a0) * 0.15915494309189535f, 1.0f);
    float m1 = fminf(fabsf(a1) * 0.15915494309189535f, 1.0f);
    *(float2*)&g_mask[b * NPIX + p] = make_float2(m0, m1);
}

// ---------------------------------------------------------------------------
// 2. fused sobel + 3x3 maxpool + per-batch min/max (16x16 output tiles)
// ---------------------------------------------------------------------------
__global__ void k_edge() {
    __shared__ float sm[20][20];   // mask tile + halo 2
    __shared__ float sb[18][18];   // sobel tile + halo 1
    __shared__ float smn[8], smx[8];

    const int b  = blockIdx.y;
    const int ti = (blockIdx.x >> 4) * 16;
    const int tj = (blockIdx.x & 15) * 16;
    const int tid = threadIdx.x;
    const float* __restrict__ m = g_mask + b * NPIX;

    for (int idx = tid; idx < 400; idx += 256) {
        int li = idx / 20, lj = idx % 20;
        int gi = min(max(ti - 2 + li, 0), SIZE - 1);
        int gj = min(max(tj - 2 + lj, 0), SIZE - 1);
        sm[li][lj] = m[gi * SIZE + gj];
    }
    __syncthreads();

    for (int idx = tid; idx < 324; idx += 256) {
        int li = idx / 18, lj = idx % 18;
        int gi = ti - 1 + li;
        int gj = tj - 1 + lj;
        float v = 0.0f;
        if (gi > 0 && gi < SIZE - 1 && gj > 0 && gj < SIZE - 1) {
            float a00 = sm[li][lj],     a01 = sm[li][lj + 1],     a02 = sm[li][lj + 2];
            float a10 = sm[li + 1][lj],                           a12 = sm[li + 1][lj + 2];
            float a20 = sm[li + 2][lj], a21 = sm[li + 2][lj + 1], a22 = sm[li + 2][lj + 2];
            float gx = 2.0f * (a00 - a02) + 4.0f * (a10 - a12) + 2.0f * (a20 - a22);
            float gy = 2.0f * (a00 - a20) + 4.0f * (a01 - a21) + 2.0f * (a02 - a22);
            v = sqrtf(fmaxf(gx * gx + gy * gy, 1e-24f));
        }
        sb[li][lj] = v;
    }
    __syncthreads();

    const int li = tid >> 4;
    const int lj = tid & 15;
    float mx = sb[li][lj];
    mx = fmaxf(mx, sb[li][lj + 1]);     mx = fmaxf(mx, sb[li][lj + 2]);
    mx = fmaxf(mx, sb[li + 1][lj]);     mx = fmaxf(mx, sb[li + 1][lj + 1]); mx = fmaxf(mx, sb[li + 1][lj + 2]);
    mx = fmaxf(mx, sb[li + 2][lj]);     mx = fmaxf(mx, sb[li + 2][lj + 1]); mx = fmaxf(mx, sb[li + 2][lj + 2]);
    g_pool[b * NPIX + (ti + li) * SIZE + (tj + lj)] = mx;

    // block-level min/max reduce then one atomic pair per block
    float lmn = mx, lmx = mx;
#pragma unroll
    for (int off = 16; off > 0; off >>= 1) {
        lmn = fminf(lmn, __shfl_xor_sync(0xffffffffu, lmn, off));
        lmx = fmaxf(lmx, __shfl_xor_sync(0xffffffffu, lmx, off));
    }
    int lane = tid & 31, wid = tid >> 5;
    if (lane == 0) { smn[wid] = lmn; smx[wid] = lmx; }
    __syncthreads();
    if (wid == 0) {
        lmn = (lane < 8) ? smn[lane] : 3.4e38f;
        lmx = (lane < 8) ? smx[lane] : 0.0f;
#pragma unroll
        for (int off = 4; off > 0; off >>= 1) {
            lmn = fminf(lmn, __shfl_xor_sync(0xffffffffu, lmn, off));
            lmx = fmaxf(lmx, __shfl_xor_sync(0xffffffffu, lmx, off));
        }
        if (lane == 0) {
            atomicMin(&g_mn[b], __float_as_uint(lmn));
            atomicMax(&g_mx[b], __float_as_uint(lmx));
        }
    }
}

// ---------------------------------------------------------------------------
// 3. per-batch normalize (vectorized)
// ---------------------------------------------------------------------------
__global__ void k_norm(float* __restrict__ out) {
    const int b = blockIdx.y;
    const int q = blockIdx.x * blockDim.x + threadIdx.x;   // float4 index
    const float mn = __uint_as_float(g_mn[b]);
    const float sc = 1.0f / (__uint_as_float(g_mx[b]) - mn + 1e-9f);
    float4 v = ((const float4*)(g_pool + b * NPIX))[q];
    v.x = (v.x - mn) * sc;
    v.y = (v.y - mn) * sc;
    v.z = (v.z - mn) * sc;
    v.w = (v.w - mn) * sc;
    ((float4*)(out + b * NPIX))[q] = v;
}

// ---------------------------------------------------------------------------
extern "C" void kernel_launch(void* const* d_in, const int* in_sizes, int n_in,
                              void* d_out, int out_size) {
    const float* contour = (const float*)d_in[0];
    float* out = (float*)d_out;

    k_init<<<1, 32>>>();
    dim3 gm(NPIX / 512, NB);
    k_mask<<<gm, 256>>>(contour);
    dim3 ge(256, NB);
    k_edge<<<ge, 256>>>();
    dim3 gn(NPIX / 4 / 256, NB);
    k_norm<<<gn, 256>>>(out);
}